// round 5
// baseline (speedup 1.0000x reference)
#include <cuda_runtime.h>

// Problem constants: N=1024, DIM=201, G=200, R=72, C=4
#define NIMG  1024
#define DIMV  201
#define GG    200
#define RR    72
#define CC    4
#define RC    288          // R*C floats per channel (contiguous)
#define F4PC  72           // float4s per channel (288/4)
#define BATCH 10           // channels per staged tile
#define NB    (GG / BATCH) // 20 batches
#define TILE_F4 (BATCH * F4PC)   // 720 float4 per tile
#define STAGES 3

// Scratch (device globals: allocation-free, graph-safe).
__device__ float        g_loss[NIMG];
__device__ unsigned int g_count = 0;   // reset by last block each run

__device__ __forceinline__ unsigned smem_u32(const void* p) {
    return (unsigned)__cvta_generic_to_shared(p);
}
__device__ __forceinline__ void cp_async16(unsigned dst, const void* src) {
    asm volatile("cp.async.cg.shared.global [%0], [%1], 16;\n"
                 :: "r"(dst), "l"(src) : "memory");
}
__device__ __forceinline__ void cp_commit() {
    asm volatile("cp.async.commit_group;\n" ::: "memory");
}
__device__ __forceinline__ void cp_wait1() {
    asm volatile("cp.async.wait_group 1;\n" ::: "memory");
}

// One block per image, 288 threads (one per (r,c) slot).
// cp.async 3-stage pipeline stages 10-channel tiles; each thread accumulates
// softmax sums for its slot from smem (conflict-free: 288 % 32 == 0).
__global__ __launch_bounds__(RC) void lane_loss_kernel(
    const float* __restrict__ x, const int* __restrict__ labels,
    float* __restrict__ out)
{
    __shared__ float4 s_tile[STAGES][TILE_F4];   // 3 x 11.52 KB
    __shared__ float  s_pos[RC];
    __shared__ int    s_top[CC];
    __shared__ int    s_down[CC];
    __shared__ bool   s_last;

    const int n   = blockIdx.x;
    const int tid = threadIdx.x;

    // ---- label parsing first (overlaps pipeline fill) ----
    if (tid < CC) {
        const int* lp = labels + (size_t)n * RC + tid;   // int32 labels
        int  top = 0, first_trans = -1;
        bool any_valid = false, prev = false;
        bool v0 = false, v1 = false, vlast = false;
        #pragma unroll
        for (int r = 0; r < RR; ++r) {
            bool v = (lp[r * CC] < GG);
            if (v && !any_valid) { top = r; any_valid = true; }
            if (r > 0 && prev && !v && first_trans < 0) first_trans = r - 1;
            if (r == 0)      v0 = v;
            if (r == 1)      v1 = v;
            if (r == RR - 1) vlast = v;
            prev = v;
        }
        bool trans0 = v0 && !v1;
        int down = trans0 ? 0
                 : (vlast ? (RR - 1)
                 : (first_trans >= 0 ? first_trans : 0));
        if (!any_valid) { top = 0; down = 0; }
        s_top[tid]  = top;
        s_down[tid] = down;
    }

    // ---- softmax-expected-position pipeline ----
    const float4* xg = (const float4*)x + (size_t)n * (DIMV * F4PC);

    // issue tile b into stage b % STAGES (each thread copies <=3 float4)
    auto issue = [&](int b) {
        const float4* src = xg + b * TILE_F4;
        unsigned dst = smem_u32(&s_tile[b % STAGES][0]);
        #pragma unroll
        for (int k = 0; k < 3; ++k) {
            int i = tid + k * RC;
            if (i < TILE_F4)
                cp_async16(dst + i * 16u, src + i);
        }
        cp_commit();
    };

    issue(0);
    issue(1);

    float s = 0.0f, p = 0.0f;
    float gw = 0.0f;
    for (int b = 0; b < NB; ++b) {
        cp_wait1();            // oldest pending group (tile b) complete
        __syncthreads();       // all threads' copies for tile b landed

        const float* t = (const float*)&s_tile[b % STAGES][0];
        #pragma unroll
        for (int j = 0; j < BATCH; ++j) {
            float e = __expf(t[j * RC + tid]);
            s += e;
            p  = fmaf(e, gw, p);
            gw += 1.0f;
        }

        if (b + 2 < NB) issue(b + 2);
        else            cp_commit();   // keep group count in lockstep
    }

    s_pos[tid] = p / s;
    __syncthreads();

    // ---- per-image loss (thread 0) ----
    if (tid == 0) {
        int tl = max(s_top[0],  max(s_top[1],  s_top[2]));
        int dl = min(s_down[0], min(s_down[1], s_down[2]));
        int tr = max(s_top[1],  max(s_top[2],  s_top[3]));
        int dr = min(s_down[1], min(s_down[2], s_down[3]));
        bool al = (tl < dl);
        bool ar = (tr < dr);

        float contrib = 0.0f;
        if (al) {
            float sl = 0.0f;
            for (int r = tl; r <= dl; ++r) {
                const float* q = &s_pos[r * CC];
                sl += fabsf(q[0] - 2.0f * q[1] + q[2]);
            }
            contrib += sl / (float)(dl - tl + 1);
        }
        if (ar) {
            float sr = 0.0f;
            for (int r = tr; r <= dr; ++r) {
                const float* q = &s_pos[r * CC];
                sr += fabsf(q[1] - 2.0f * q[2] + q[3]);
            }
            contrib += sr / (float)(dr - tr + 1);
        }
        float denom = (al && ar) ? (2.0f * (float)RR) : (float)RR;
        g_loss[n] = contrib / denom;

        __threadfence();
        unsigned int old = atomicAdd(&g_count, 1u);
        s_last = (old == NIMG - 1);
    }
    __syncthreads();

    // ---- last block: deterministic fixed-order global reduction ----
    if (s_last) {
        float sum = 0.0f;
        int   cnt = 0;
        #pragma unroll
        for (int k = 0; k < 4; ++k) {
            int i = tid + k * RC;          // covers 0..1151
            if (i < NIMG) {
                float v = g_loss[i];
                sum += v;
                cnt += (v != 0.0f) ? 1 : 0;
            }
        }
        #pragma unroll
        for (int o = 16; o > 0; o >>= 1) {
            sum += __shfl_down_sync(0xffffffffu, sum, o);
            cnt += __shfl_down_sync(0xffffffffu, cnt, o);
        }
        __shared__ float wsum[9];
        __shared__ int   wcnt[9];
        const int wid = tid >> 5, lid = tid & 31;
        if (lid == 0) { wsum[wid] = sum; wcnt[wid] = cnt; }
        __syncthreads();
        if (tid == 0) {
            float ts = 0.0f; int tc = 0;
            #pragma unroll
            for (int w = 0; w < 9; ++w) { ts += wsum[w]; tc += wcnt[w]; }
            out[0] = (tc > 0) ? (ts / (float)tc) : 0.0f;
            g_count = 0;   // reset for next graph replay
        }
    }
}

extern "C" void kernel_launch(void* const* d_in, const int* in_sizes, int n_in,
                              void* d_out, int out_size)
{
    const float* x      = (const float*)d_in[0];   // [1024, 201, 72, 4] f32
    const int*   labels = (const int*)d_in[1];     // [1024, 72, 4] int32
    float*       out    = (float*)d_out;           // scalar f32

    lane_loss_kernel<<<NIMG, RC>>>(x, labels, out);
}

// round 6
// speedup vs baseline: 1.2471x; 1.2471x over previous
#include <cuda_runtime.h>

// Problem constants: N=1024, DIM=201, G=200, R=72, C=4
#define NIMG 1024
#define DIMV 201
#define GG   200
#define RR   72
#define CC   4
#define RC   288    // R*C, contiguous innermost block of x per (n, g)
#define NGC  4      // g-chunks per image (200 / 50)
#define GPC  50     // channels per g-chunk
#define NSG  72     // slot-groups (288 slots / 4 per float4)

// Scratch (device globals: allocation-free, graph-safe).
__device__ float        g_loss[NIMG];
__device__ unsigned int g_count = 0;   // reset by last block each run

// One block per image, 288 threads, 7 blocks/SM -> all 1024 blocks in ONE wave.
__global__ __launch_bounds__(RC, 7) void lane_loss_kernel(
    const float* __restrict__ x, const int* __restrict__ labels,
    float* __restrict__ out)
{
    __shared__ float sS[NGC][RC];     // partial sum(exp)
    __shared__ float sP[NGC][RC];     // partial sum(g*exp)
    __shared__ float s_pos[RC];
    __shared__ int   s_top[CC];
    __shared__ int   s_down[CC];
    __shared__ bool  s_last;

    const int n   = blockIdx.x;
    const int tid = threadIdx.x;
    const int gc  = tid / NSG;        // 0..3
    const int sg  = tid % NSG;        // 0..71

    // ---- Phase 1: exp accumulation, fully unrolled (g weights = immediates) ----
    {
        const float4* xp = (const float4*)(x + (size_t)n * (DIMV * RC))
                           + (unsigned)(gc * GPC) * NSG + sg;
        float s0 = 0.f, s1 = 0.f, s2 = 0.f, s3 = 0.f;
        float p0 = 0.f, p1 = 0.f, p2 = 0.f, p3 = 0.f;
        const float gb = (float)(gc * GPC);

        #pragma unroll
        for (int i = 0; i < GPC; ++i) {
            float4 v = xp[(unsigned)i * NSG];   // immediate offset off one base
            float gi = gb + (float)i;           // compile-time per unrolled iter
            float e0 = __expf(v.x), e1 = __expf(v.y);
            float e2 = __expf(v.z), e3 = __expf(v.w);
            s0 += e0; p0 = fmaf(e0, gi, p0);
            s1 += e1; p1 = fmaf(e1, gi, p1);
            s2 += e2; p2 = fmaf(e2, gi, p2);
            s3 += e3; p3 = fmaf(e3, gi, p3);
        }
        const int base = sg * 4;
        sS[gc][base + 0] = s0;  sP[gc][base + 0] = p0;
        sS[gc][base + 1] = s1;  sP[gc][base + 1] = p1;
        sS[gc][base + 2] = s2;  sP[gc][base + 2] = p2;
        sS[gc][base + 3] = s3;  sP[gc][base + 3] = p3;
    }

    // ---- Phase 2: parse top/down per lane (threads 0..3) ----
    if (tid < CC) {
        const int* lp = labels + (size_t)n * RC + tid;   // int32 labels
        int  top = 0, first_trans = -1;
        bool any_valid = false, prev = false;
        bool v0 = false, v1 = false, vlast = false;
        #pragma unroll
        for (int r = 0; r < RR; ++r) {
            bool v = (lp[r * CC] < GG);
            if (v && !any_valid) { top = r; any_valid = true; }
            if (r > 0 && prev && !v && first_trans < 0) first_trans = r - 1;
            if (r == 0)      v0 = v;
            if (r == 1)      v1 = v;
            if (r == RR - 1) vlast = v;
            prev = v;
        }
        bool trans0 = v0 && !v1;
        int down = trans0 ? 0
                 : (vlast ? (RR - 1)
                 : (first_trans >= 0 ? first_trans : 0));
        if (!any_valid) { top = 0; down = 0; }
        s_top[tid]  = top;
        s_down[tid] = down;
    }
    __syncthreads();

    // Combine gc-partials -> pos per slot
    {
        float s = sS[0][tid] + sS[1][tid] + sS[2][tid] + sS[3][tid];
        float p = sP[0][tid] + sP[1][tid] + sP[2][tid] + sP[3][tid];
        s_pos[tid] = p / s;
    }
    __syncthreads();

    // ---- Phase 3: per-image loss (thread 0) ----
    if (tid == 0) {
        int tl = max(s_top[0],  max(s_top[1],  s_top[2]));
        int dl = min(s_down[0], min(s_down[1], s_down[2]));
        int tr = max(s_top[1],  max(s_top[2],  s_top[3]));
        int dr = min(s_down[1], min(s_down[2], s_down[3]));
        bool al = (tl < dl);
        bool ar = (tr < dr);

        float contrib = 0.0f;
        if (al) {
            float sl = 0.0f;
            for (int r = tl; r <= dl; ++r) {
                const float* q = &s_pos[r * CC];
                sl += fabsf(q[0] - 2.0f * q[1] + q[2]);
            }
            contrib += sl / (float)(dl - tl + 1);
        }
        if (ar) {
            float sr = 0.0f;
            for (int r = tr; r <= dr; ++r) {
                const float* q = &s_pos[r * CC];
                sr += fabsf(q[1] - 2.0f * q[2] + q[3]);
            }
            contrib += sr / (float)(dr - tr + 1);
        }
        float denom = (al && ar) ? (2.0f * (float)RR) : (float)RR;
        g_loss[n] = contrib / denom;

        __threadfence();
        unsigned int old = atomicAdd(&g_count, 1u);
        s_last = (old == NIMG - 1);
    }
    __syncthreads();

    // ---- Phase 4: last block reduces all per-image losses ----
    if (s_last) {
        float sum = 0.0f;
        int   cnt = 0;
        #pragma unroll
        for (int k = 0; k < 4; ++k) {
            int i = tid + k * RC;            // covers 0..1151
            if (i < NIMG) {
                float v = g_loss[i];
                sum += v;
                cnt += (v != 0.0f) ? 1 : 0;
            }
        }
        #pragma unroll
        for (int o = 16; o > 0; o >>= 1) {
            sum += __shfl_down_sync(0xffffffffu, sum, o);
            cnt += __shfl_down_sync(0xffffffffu, cnt, o);
        }
        __shared__ float wsum[9];
        __shared__ int   wcnt[9];
        const int wid = tid >> 5, lid = tid & 31;
        if (lid == 0) { wsum[wid] = sum; wcnt[wid] = cnt; }
        __syncthreads();
        if (tid == 0) {
            float ts = 0.0f; int tc = 0;
            #pragma unroll
            for (int w = 0; w < 9; ++w) { ts += wsum[w]; tc += wcnt[w]; }
            out[0] = (tc > 0) ? (ts / (float)tc) : 0.0f;
            g_count = 0;   // reset for next graph replay
        }
    }
}

extern "C" void kernel_launch(void* const* d_in, const int* in_sizes, int n_in,
                              void* d_out, int out_size)
{
    const float* x      = (const float*)d_in[0];   // [1024, 201, 72, 4] f32
    const int*   labels = (const int*)d_in[1];     // [1024, 72, 4] int32
    float*       out    = (float*)d_out;           // scalar f32

    lane_loss_kernel<<<NIMG, RC>>>(x, labels, out);
}

// round 7
// speedup vs baseline: 1.2535x; 1.0052x over previous
#include <cuda_runtime.h>

// Problem constants: N=1024, DIM=201, G=200, R=72, C=4
#define NIMG 1024
#define DIMV 201
#define GG   200
#define RR   72
#define CC   4
#define RC   288    // R*C, contiguous innermost block of x per (n, g)
#define NGC  4      // g-chunks per image (200 / 50)
#define GPC  50     // channels per g-chunk
#define NSG  72     // slot-groups (288 slots / 4 per float4)

// Scratch (device globals: allocation-free, graph-safe).
__device__ float        g_loss[NIMG];
__device__ unsigned int g_count = 0;   // reset by last block each run

// One block per image, 288 threads, 7 blocks/SM -> all 1024 blocks in ONE wave.
__global__ __launch_bounds__(RC, 7) void lane_loss_kernel(
    const float* __restrict__ x, const int* __restrict__ labels,
    float* __restrict__ out)
{
    __shared__ float sS[NGC][RC];          // partial sum(exp)
    __shared__ float sP[NGC][RC];          // partial sum(g*exp)
    __shared__ float s_pos[RC];            // row-major: s_pos[r*4+c], float4/row
    __shared__ unsigned char s_valid[RC];
    __shared__ int   s_top[CC];
    __shared__ int   s_down[CC];
    __shared__ bool  s_last;

    const int n   = blockIdx.x;
    const int tid = threadIdx.x;
    const int gc  = tid / NSG;        // 0..3
    const int sg  = tid % NSG;        // 0..71

    // ---- label validity: one coalesced load per thread ----
    s_valid[tid] = (labels[(size_t)n * RC + tid] < GG) ? 1 : 0;

    // ---- Phase 1: exp accumulation, fully unrolled, streaming loads ----
    {
        const float4* xp = (const float4*)(x + (size_t)n * (DIMV * RC))
                           + (unsigned)(gc * GPC) * NSG + sg;
        float s0 = 0.f, s1 = 0.f, s2 = 0.f, s3 = 0.f;
        float p0 = 0.f, p1 = 0.f, p2 = 0.f, p3 = 0.f;
        const float gb = (float)(gc * GPC);

        #pragma unroll
        for (int i = 0; i < GPC; ++i) {
            float4 v = __ldcs(xp + (unsigned)i * NSG);   // evict-first streaming
            float gi = gb + (float)i;
            float e0 = __expf(v.x), e1 = __expf(v.y);
            float e2 = __expf(v.z), e3 = __expf(v.w);
            s0 += e0; p0 = fmaf(e0, gi, p0);
            s1 += e1; p1 = fmaf(e1, gi, p1);
            s2 += e2; p2 = fmaf(e2, gi, p2);
            s3 += e3; p3 = fmaf(e3, gi, p3);
        }
        const int base = sg * 4;
        sS[gc][base + 0] = s0;  sP[gc][base + 0] = p0;
        sS[gc][base + 1] = s1;  sP[gc][base + 1] = p1;
        sS[gc][base + 2] = s2;  sP[gc][base + 2] = p2;
        sS[gc][base + 3] = s3;  sP[gc][base + 3] = p3;
    }
    __syncthreads();

    // ---- combine partials -> pos; threads 0..3 also scan validity ----
    {
        float s = sS[0][tid] + sS[1][tid] + sS[2][tid] + sS[3][tid];
        float p = sP[0][tid] + sP[1][tid] + sP[2][tid] + sP[3][tid];
        s_pos[tid] = p / s;
    }
    if (tid < CC) {
        int  top = 0, first_trans = -1;
        bool any_valid = false, prev = false;
        bool v0 = false, v1 = false, vlast = false;
        #pragma unroll
        for (int r = 0; r < RR; ++r) {
            bool v = (s_valid[r * CC + tid] != 0);
            if (v && !any_valid) { top = r; any_valid = true; }
            if (r > 0 && prev && !v && first_trans < 0) first_trans = r - 1;
            if (r == 0)      v0 = v;
            if (r == 1)      v1 = v;
            if (r == RR - 1) vlast = v;
            prev = v;
        }
        bool trans0 = v0 && !v1;
        int down = trans0 ? 0
                 : (vlast ? (RR - 1)
                 : (first_trans >= 0 ? first_trans : 0));
        if (!any_valid) { top = 0; down = 0; }
        s_top[tid]  = top;
        s_down[tid] = down;
    }
    __syncthreads();

    // ---- per-image loss: parallel over warp 0 ----
    if (tid < 32) {
        const int tl = max(s_top[0],  max(s_top[1],  s_top[2]));
        const int dl = min(s_down[0], min(s_down[1], s_down[2]));
        const int tr = max(s_top[1],  max(s_top[2],  s_top[3]));
        const int dr = min(s_down[1], min(s_down[2], s_down[3]));
        const bool al = (tl < dl);
        const bool ar = (tr < dr);

        float suml = 0.0f, sumr = 0.0f;
        const float4* pos4 = (const float4*)s_pos;
        #pragma unroll
        for (int k = 0; k < 3; ++k) {
            int r = tid + k * 32;
            if (r < RR) {
                float4 q = pos4[r];                       // LDS.128, one row
                float ddl = fabsf(q.x - 2.0f * q.y + q.z);
                float ddr = fabsf(q.y - 2.0f * q.z + q.w);
                if (r >= tl && r <= dl) suml += ddl;
                if (r >= tr && r <= dr) sumr += ddr;
            }
        }
        #pragma unroll
        for (int o = 16; o > 0; o >>= 1) {
            suml += __shfl_down_sync(0xffffffffu, suml, o);
            sumr += __shfl_down_sync(0xffffffffu, sumr, o);
        }
        if (tid == 0) {
            float contrib = 0.0f;
            if (al) contrib += suml / (float)(dl - tl + 1);
            if (ar) contrib += sumr / (float)(dr - tr + 1);
            float denom = (al && ar) ? (2.0f * (float)RR) : (float)RR;
            g_loss[n] = contrib / denom;

            __threadfence();
            unsigned int old = atomicAdd(&g_count, 1u);
            s_last = (old == NIMG - 1);
        }
    }
    __syncthreads();

    // ---- last block: deterministic fixed-order global reduction ----
    if (s_last) {
        float sum = 0.0f;
        int   cnt = 0;
        #pragma unroll
        for (int k = 0; k < 4; ++k) {
            int i = tid + k * RC;            // covers 0..1151
            if (i < NIMG) {
                float v = g_loss[i];
                sum += v;
                cnt += (v != 0.0f) ? 1 : 0;
            }
        }
        #pragma unroll
        for (int o = 16; o > 0; o >>= 1) {
            sum += __shfl_down_sync(0xffffffffu, sum, o);
            cnt += __shfl_down_sync(0xffffffffu, cnt, o);
        }
        __shared__ float wsum[9];
        __shared__ int   wcnt[9];
        const int wid = tid >> 5, lid = tid & 31;
        if (lid == 0) { wsum[wid] = sum; wcnt[wid] = cnt; }
        __syncthreads();
        if (tid == 0) {
            float ts = 0.0f; int tc = 0;
            #pragma unroll
            for (int w = 0; w < 9; ++w) { ts += wsum[w]; tc += wcnt[w]; }
            out[0] = (tc > 0) ? (ts / (float)tc) : 0.0f;
            g_count = 0;   // reset for next graph replay
        }
    }
}

extern "C" void kernel_launch(void* const* d_in, const int* in_sizes, int n_in,
                              void* d_out, int out_size)
{
    const float* x      = (const float*)d_in[0];   // [1024, 201, 72, 4] f32
    const int*   labels = (const int*)d_in[1];     // [1024, 72, 4] int32
    float*       out    = (float*)d_out;           // scalar f32

    lane_loss_kernel<<<NIMG, RC>>>(x, labels, out);
}